// round 16
// baseline (speedup 1.0000x reference)
#include <cuda_runtime.h>
#include <cstdint>

#define TOKENS 4096
#define HID    4096
#define VOCAB  32000
#define NCHUNK 16
#define MT     32      // 4096/128 m tiles
#define NT128  250     // 32000/128 n tiles
#define KT64   64      // 4096/64 k stage-chunks
#define GRID   296     // persistent CTAs = 2/SM x 148 SMs
#define NTILES 8000    // MT * NT128

// ---------------- device scratch (static; no cudaMalloc) -------------------
// bf16 fragment-ordered operands for mma.sync m16n8k16:
// g_xa: A block (kt,mt) = 16384 B at ((kt*MT+mt)<<14)
//   off = (ka*8+ma)*512 + ((mm&7)*4 + ((kk&7)>>1))*16 + ((kk>>3)*2 + (mm>>3))*4
// g_wb: B block (kt,nt) = 16384 B at ((kt*NT128+nt)<<14), 128-wide, NA-PAIRED:
//   off = (ka*8 + np)*512 + lane*16,  lane = nn*4 + p
__device__ __align__(16) unsigned char g_xa[(size_t)TOKENS * HID * 2];
__device__ __align__(16) unsigned char g_wb[(size_t)VOCAB * HID * 2];
__device__ float g_ws[VOCAB];
__device__ float g_cmaxp[4 * NCHUNK * HID];   // [rg][chunk][ch] partials
__device__ float g_part[NCHUNK * 16];
__device__ float g_tmaxf[NCHUNK];
__device__ float g_sx[NCHUNK * HID];
__device__ float g_mult[NCHUNK * HID];

// ------------------------------ helpers ------------------------------------
__device__ __forceinline__ uint32_t smem_u32(const void* p) {
    uint32_t a;
    asm("{ .reg .u64 t; cvta.to.shared.u64 t, %1; cvt.u32.u64 %0, t; }"
        : "=r"(a) : "l"(p));
    return a;
}
__device__ __forceinline__ float qclamp(float x, float s) {
    // matches jnp.clip(jnp.round(x/s), -8, 7), round-half-to-even, rn divide
    return fminf(fmaxf(rintf(__fdiv_rn(x, s)), -8.0f), 7.0f);
}
__device__ __forceinline__ uint32_t bf16x2(float lo, float hi) {
    uint32_t r;
    asm("cvt.rn.bf16x2.f32 %0, %1, %2;" : "=r"(r) : "f"(hi), "f"(lo));
    return r;
}
__device__ __forceinline__ void mma16816(float* c, const uint32_t* a,
                                         const uint32_t* b) {
    asm volatile(
        "mma.sync.aligned.m16n8k16.row.col.f32.bf16.bf16.f32 "
        "{%0,%1,%2,%3}, {%4,%5,%6,%7}, {%8,%9}, {%0,%1,%2,%3};"
        : "+f"(c[0]), "+f"(c[1]), "+f"(c[2]), "+f"(c[3])
        : "r"(a[0]), "r"(a[1]), "r"(a[2]), "r"(a[3]), "r"(b[0]), "r"(b[1]));
}
#define CP_ASYNC16(dst_u32, src_ptr) \
    asm volatile("cp.async.cg.shared.global [%0], [%1], 16;" \
                 :: "r"(dst_u32), "l"(src_ptr) : "memory")
#define CP_COMMIT()  asm volatile("cp.async.commit_group;" ::: "memory")
#define CP_WAIT1()   asm volatile("cp.async.wait_group 1;" ::: "memory")

// ------------------------------ launch 1: X stats ---------------------------
__global__ void cmax_kernel(const float* __restrict__ X) {
    const int b = blockIdx.x;
    const int c = b >> 4, rg = (b >> 2) & 3, cg = b & 3;
    const int t = threadIdx.x;
    const int col4 = cg * 256 + t;                 // float4 column index
    const float4* p = reinterpret_cast<const float4*>(X) +
                      (size_t)(c * 256 + rg * 64) * 1024 + col4;
    float4 m4 = make_float4(0.f, 0.f, 0.f, 0.f);
#pragma unroll 8
    for (int r = 0; r < 64; r++) {
        float4 f = p[(size_t)r * 1024];
        m4.x = fmaxf(m4.x, fabsf(f.x)); m4.y = fmaxf(m4.y, fabsf(f.y));
        m4.z = fmaxf(m4.z, fabsf(f.z)); m4.w = fmaxf(m4.w, fabsf(f.w));
    }
    reinterpret_cast<float4*>(g_cmaxp)[(size_t)(rg * NCHUNK + c) * 1024 + col4] = m4;
    float m = fmaxf(fmaxf(m4.x, m4.y), fmaxf(m4.z, m4.w));
    __shared__ float red[256];
    red[t] = m;
    __syncthreads();
    for (int s = 128; s > 0; s >>= 1) {
        if (t < s) red[t] = fmaxf(red[t], red[t + s]);
        __syncthreads();
    }
    if (t == 0) g_part[c * 16 + rg * 4 + cg] = red[0];
}

// ------------------------------ launch 2: scales ----------------------------
__global__ void chunk_scales_kernel() {
    const int idx = blockIdx.x * 256 + threadIdx.x;   // NCHUNK*HID = 65536
    const int c = idx >> 12, ch = idx & 4095;
    float tmax = 0.0f;
#pragma unroll
    for (int j = 0; j < 16; j++) tmax = fmaxf(tmax, g_part[c * 16 + j]);
    if (ch == 0) g_tmaxf[c] = tmax;
    float cm = 0.0f;
#pragma unroll
    for (int rg = 0; rg < 4; rg++)
        cm = fmaxf(cm, g_cmaxp[(size_t)(rg * NCHUNK + c) * HID + ch]);
    int b = 0;
#pragma unroll
    for (int i = 0; i < 13; i++) b += (cm > ldexpf(tmax, i - 13)) ? 1 : 0;
    g_sx[idx]   = fmaxf(__fdiv_rn(ldexpf(tmax, b - 13), 7.0f), 1e-9f);
    g_mult[idx] = ldexpf(1.0f, b - 8);   // exact pow2 emit multiplier
}

// ------------------------------ launch 3: pack (W + X fused) ----------------
// blocks [0,2000): weight scale+pack, warp per ROW PAIR (v, v+8)
// blocks [2000,4048): activation pack (mt = b&31, kt = b>>5), float4 loads
__global__ void pack_kernel(const float* __restrict__ W,
                            const float* __restrict__ X) {
    if (blockIdx.x < 2000) {
        const int w = threadIdx.x >> 5, lane = threadIdx.x & 31;
        const int v = blockIdx.x * 16 + w;          // rows v and v+8
        const float4* rA = reinterpret_cast<const float4*>(W + (size_t)v * HID);
        const float4* rB = reinterpret_cast<const float4*>(W + (size_t)(v + 8) * HID);
        float mA = 0.0f, mB = 0.0f;
#pragma unroll
        for (int j = 0; j < 32; j++) {
            float4 a = rA[lane + j * 32];
            float4 b = rB[lane + j * 32];
            mA = fmaxf(mA, fmaxf(fmaxf(fabsf(a.x), fabsf(a.y)),
                                 fmaxf(fabsf(a.z), fabsf(a.w))));
            mB = fmaxf(mB, fmaxf(fmaxf(fabsf(b.x), fabsf(b.y)),
                                 fmaxf(fabsf(b.z), fabsf(b.w))));
        }
#pragma unroll
        for (int s = 16; s > 0; s >>= 1) {
            mA = fmaxf(mA, __shfl_xor_sync(0xFFFFFFFFu, mA, s));
            mB = fmaxf(mB, __shfl_xor_sync(0xFFFFFFFFu, mB, s));
        }
        const float scA = fmaxf(__fdiv_rn(__shfl_sync(0xFFFFFFFFu, mA, 0), 7.0f),
                                1e-9f);
        const float scB = fmaxf(__fdiv_rn(__shfl_sync(0xFFFFFFFFu, mB, 0), 7.0f),
                                1e-9f);
        if (lane == 0) { g_ws[v] = scA; g_ws[v + 8] = scB; }
        const int nt = v >> 7, np = ((v & 127) >> 3) >> 1, nn = v & 7;
        unsigned char* base = g_wb + ((size_t)nt << 14) + np * 512 + nn * 64;
#pragma unroll 2
        for (int i = 0; i < 8; i++) {
            const int c = i * 32 + lane;          // 16-k chunk index
            const int kt = c >> 2, ka = c & 3;
            const float4 a0 = rA[c * 4 + 0], a1 = rA[c * 4 + 1];
            const float4 a2 = rA[c * 4 + 2], a3 = rA[c * 4 + 3];
            const float4 b0 = rB[c * 4 + 0], b1 = rB[c * 4 + 1];
            const float4 b2 = rB[c * 4 + 2], b3 = rB[c * 4 + 3];
            uint4 u0, u1, u2, u3;
            u0.x = bf16x2(qclamp(a0.x, scA), qclamp(a0.y, scA));
            u0.y = bf16x2(qclamp(a2.x, scA), qclamp(a2.y, scA));
            u0.z = bf16x2(qclamp(b0.x, scB), qclamp(b0.y, scB));
            u0.w = bf16x2(qclamp(b2.x, scB), qclamp(b2.y, scB));
            u1.x = bf16x2(qclamp(a0.z, scA), qclamp(a0.w, scA));
            u1.y = bf16x2(qclamp(a2.z, scA), qclamp(a2.w, scA));
            u1.z = bf16x2(qclamp(b0.z, scB), qclamp(b0.w, scB));
            u1.w = bf16x2(qclamp(b2.z, scB), qclamp(b2.w, scB));
            u2.x = bf16x2(qclamp(a1.x, scA), qclamp(a1.y, scA));
            u2.y = bf16x2(qclamp(a3.x, scA), qclamp(a3.y, scA));
            u2.z = bf16x2(qclamp(b1.x, scB), qclamp(b1.y, scB));
            u2.w = bf16x2(qclamp(b3.x, scB), qclamp(b3.y, scB));
            u3.x = bf16x2(qclamp(a1.z, scA), qclamp(a1.w, scA));
            u3.y = bf16x2(qclamp(a3.z, scA), qclamp(a3.w, scA));
            u3.z = bf16x2(qclamp(b1.z, scB), qclamp(b1.w, scB));
            u3.w = bf16x2(qclamp(b3.z, scB), qclamp(b3.w, scB));
            unsigned char* dst =
                base + (size_t)kt * NT128 * 16384 + ka * 4096;
            *reinterpret_cast<uint4*>(dst)      = u0;  // p=0
            *reinterpret_cast<uint4*>(dst + 16) = u1;  // p=1
            *reinterpret_cast<uint4*>(dst + 32) = u2;  // p=2
            *reinterpret_cast<uint4*>(dst + 48) = u3;  // p=3
        }
    } else {
        // activation pack block (mt, kt): 128 rows x 64 K -> 16 KB fragment tile
        const int b2 = blockIdx.x - 2000;
        const int mt = b2 & 31, kt = b2 >> 5;
        const int t = threadIdx.x;
        __shared__ __align__(16) unsigned char stg[16384];
        const int r = t >> 1, hh = (t & 1) * 32;
        const int token = mt * 128 + r;
        const int chunk = token >> 8;
        const float4* x4 = reinterpret_cast<const float4*>(
            X + (size_t)token * HID + kt * 64 + hh);
        const float4* s4 = reinterpret_cast<const float4*>(
            g_sx + (size_t)chunk * HID + kt * 64 + hh);
        const float4* m4 = reinterpret_cast<const float4*>(
            g_mult + (size_t)chunk * HID + kt * 64 + hh);
        const int mm = r & 15, ma = r >> 4;
#pragma unroll
        for (int i = 0; i < 8; i++) {
            const float4 xv = x4[i], sv = s4[i], mv = m4[i];
            const int kl = hh + 4 * i;
            const int ka = kl >> 4, kk = kl & 15;
            const float e0 = qclamp(xv.x, sv.x) * mv.x;
            const float e1 = qclamp(xv.y, sv.y) * mv.y;
            const float e2 = qclamp(xv.z, sv.z) * mv.z;
            const float e3 = qclamp(xv.w, sv.w) * mv.w;
            const uint32_t base0 = (uint32_t)((ka * 8 + ma) * 512 +
                                   (mm & 7) * 64 + (mm >> 3) * 4);
            const uint32_t off0 = base0 + ((kk & 7) >> 1) * 16 + (kk >> 3) * 8;
            const int k2 = kk + 2;
            const uint32_t off1 = base0 + ((k2 & 7) >> 1) * 16 + (k2 >> 3) * 8;
            *reinterpret_cast<uint32_t*>(stg + off0) = bf16x2(e0, e1);
            *reinterpret_cast<uint32_t*>(stg + off1) = bf16x2(e2, e3);
        }
        __syncthreads();
        uint4* dst = reinterpret_cast<uint4*>(g_xa + ((size_t)(kt * MT + mt) << 14));
        const uint4* src = reinterpret_cast<const uint4*>(stg);
#pragma unroll
        for (int i = 0; i < 4; i++) dst[t + i * 256] = src[t + i * 256];
    }
}

// --------------------------------- GEMM (launch 4) --------------------------
// PERSISTENT: 296 CTAs (2/SM), each owns tiles g = bid + 296*i (27-28 tiles).
// Flat software pipeline across tiles: fetch(it+2) crosses tile boundaries,
// so the next tile's stages prefetch under this tile's tail + epilogue.
// Mainloop body identical to R14 (fetch at END — ratified). 128x128 tile,
// 4 warps of 64x64, 3 stages x 32 KB.
#define STAGES 3
#define STG_BYTES 32768   // A 16 KB + B 16 KB

__global__ void __launch_bounds__(128, 2) gemm_kernel(float* __restrict__ out) {
    extern __shared__ __align__(16) unsigned char dyn[];
    __shared__ float s_sw[128];
    const int tid = threadIdx.x;
    const int wid = tid >> 5, lid = tid & 31;
    const int wm = wid >> 1, wn = wid & 1;   // 2m x 2n warps of 64x64
    const uint32_t sbase = smem_u32(dyn);

    int g = blockIdx.x;                       // current tile id
    int mt = g & 31, nt = g >> 5;
    const int ntiles = (NTILES - g + GRID - 1) / GRID;

    s_sw[tid] = g_ws[nt * 128 + tid];

    auto fetch = [&](int s, int fg, int fkt) {
        const uint32_t d = sbase + s * STG_BYTES + tid * 16;
        const unsigned char* a =
            g_xa + (((size_t)fkt * MT + (fg & 31)) << 14) + tid * 16;
        const unsigned char* b =
            g_wb + (((size_t)fkt * NT128 + (fg >> 5)) << 14) + tid * 16;
#pragma unroll
        for (int i = 0; i < 8; i++) CP_ASYNC16(d + i * 2048, a + i * 2048);
#pragma unroll
        for (int i = 0; i < 8; i++)
            CP_ASYNC16(d + 16384 + i * 2048, b + i * 2048);
    };

    float acc[4][8][4];
#pragma unroll
    for (int i = 0; i < 4; i++)
#pragma unroll
        for (int j = 0; j < 8; j++)
#pragma unroll
            for (int k = 0; k < 4; k++) acc[i][j][k] = 0.0f;

    fetch(0, g, 0); CP_COMMIT();
    fetch(1, g, 1); CP_COMMIT();

    int fg = g, fkt = 2;                      // next fetch position (flat it+2)
    int stage = 0;
    const int it_total = ntiles * KT64;
#pragma unroll 1
    for (int it = 0; it < it_total; it++) {
        const int kt = it & 63;
        CP_WAIT1();
        __syncthreads();
        const unsigned char* st = dyn + stage * STG_BYTES;
#pragma unroll
        for (int ka = 0; ka < 4; ka++) {
            uint32_t af[4][4], bf[8][2];
#pragma unroll
            for (int ma = 0; ma < 4; ma++) {
                const uint4 q = *reinterpret_cast<const uint4*>(
                    st + (ka * 8 + wm * 4 + ma) * 512 + lid * 16);
                af[ma][0] = q.x; af[ma][1] = q.y; af[ma][2] = q.z; af[ma][3] = q.w;
            }
#pragma unroll
            for (int np = 0; np < 4; np++) {     // na pair: one LDS.128 for 2 na
                const uint4 q = *reinterpret_cast<const uint4*>(
                    st + 16384 + (ka * 8 + wn * 4 + np) * 512 + lid * 16);
                bf[2 * np][0] = q.x;     bf[2 * np][1] = q.y;
                bf[2 * np + 1][0] = q.z; bf[2 * np + 1][1] = q.w;
            }
#pragma unroll
            for (int ma = 0; ma < 4; ma++)
#pragma unroll
                for (int na = 0; na < 8; na++)
                    mma16816(acc[ma][na], af[ma], bf[na]);
        }
        // fetch flat it+2 (crosses tile boundary automatically); empty commit
        // when exhausted keeps wait_group accounting aligned.
        if (fg < NTILES) {
            int ws = stage + 2; if (ws >= STAGES) ws -= STAGES;
            fetch(ws, fg, fkt);
            if (++fkt == KT64) { fkt = 0; fg += GRID; }
        }
        CP_COMMIT();
        if (++stage == STAGES) stage = 0;

        if (kt == 63) {
            // epilogue for tile (mt, nt): acc * alpha[chunk] * sw[v]
            const float alpha = __fdiv_rn(g_tmaxf[mt >> 1], 7.0f) * 0.03125f;
            const int row_base = mt * 128 + wm * 64;
            const int col_cta = nt * 128;
#pragma unroll
            for (int ma = 0; ma < 4; ma++) {
#pragma unroll
                for (int na = 0; na < 8; na++) {
                    const int r0 = row_base + ma * 16 + (lid >> 2);
                    const int c0 = wn * 64 + na * 8 + (lid & 3) * 2;
                    const float f0 = s_sw[c0] * alpha, f1 = s_sw[c0 + 1] * alpha;
                    float* p = out + (size_t)r0 * VOCAB + col_cta + c0;
                    float2 v0, v1;
                    v0.x = acc[ma][na][0] * f0; v0.y = acc[ma][na][1] * f1;
                    v1.x = acc[ma][na][2] * f0; v1.y = acc[ma][na][3] * f1;
                    *reinterpret_cast<float2*>(p) = v0;
                    *reinterpret_cast<float2*>(p + (size_t)8 * VOCAB) = v1;
                    acc[ma][na][0] = 0.0f; acc[ma][na][1] = 0.0f;
                    acc[ma][na][2] = 0.0f; acc[ma][na][3] = 0.0f;
                }
            }
            g += GRID;
            __syncthreads();               // all reads of s_sw done
            if (g < NTILES) {
                mt = g & 31; nt = g >> 5;
                s_sw[tid] = g_ws[nt * 128 + tid];
                // visibility ordered by the next iteration's __syncthreads
            }
        }
    }
}

// ------------------------------- launcher ----------------------------------
extern "C" void kernel_launch(void* const* d_in, const int* in_sizes, int n_in,
                              void* d_out, int out_size) {
    const float* hs = (const float*)d_in[0];   // [2,2048,4096]
    const float* W  = (const float*)d_in[1];   // [32000,4096]
    float* out = (float*)d_out;

    cudaFuncSetAttribute(gemm_kernel,
                         cudaFuncAttributeMaxDynamicSharedMemorySize,
                         STAGES * STG_BYTES);

    // 4 launches: gemm stays at ncu's profiled slot (-s 5 -c 1).
    cmax_kernel<<<256, 256>>>(hs);
    chunk_scales_kernel<<<NCHUNK * HID / 256, 256>>>();
    pack_kernel<<<4048, 256>>>(W, hs);
    gemm_kernel<<<GRID, 128, STAGES * STG_BYTES>>>(out);
}

// round 17
// speedup vs baseline: 1.0582x; 1.0582x over previous
#include <cuda_runtime.h>
#include <cstdint>

#define TOKENS 4096
#define HID    4096
#define VOCAB  32000
#define NCHUNK 16
#define MT     32      // 4096/128 m tiles
#define NT128  250     // 32000/128 n tiles
#define KT64   64      // 4096/64 k stage-chunks

// ---------------- device scratch (static; no cudaMalloc) -------------------
// bf16 fragment-ordered operands for mma.sync m16n8k16:
// g_xa: A block (kt,mt) = 16384 B at ((kt*MT+mt)<<14)
//   off = (ka*8+ma)*512 + ((mm&7)*4 + ((kk&7)>>1))*16 + ((kk>>3)*2 + (mm>>3))*4
// g_wb: B block (kt,nt) = 16384 B at ((kt*NT128+nt)<<14), 128-wide, NA-PAIRED:
//   off = (ka*8 + np)*512 + lane*16,  lane = nn*4 + p
__device__ __align__(16) unsigned char g_xa[(size_t)TOKENS * HID * 2];
__device__ __align__(16) unsigned char g_wb[(size_t)VOCAB * HID * 2];
__device__ float g_ws[VOCAB];
__device__ float g_cmaxp[4 * NCHUNK * HID];   // [rg][chunk][ch] partials
__device__ float g_part[NCHUNK * 16];
__device__ float g_tmaxf[NCHUNK];
__device__ float g_sx[NCHUNK * HID];
__device__ float g_mult[NCHUNK * HID];

// ------------------------------ helpers ------------------------------------
__device__ __forceinline__ uint32_t smem_u32(const void* p) {
    uint32_t a;
    asm("{ .reg .u64 t; cvta.to.shared.u64 t, %1; cvt.u32.u64 %0, t; }"
        : "=r"(a) : "l"(p));
    return a;
}
__device__ __forceinline__ float qclamp(float x, float s) {
    // matches jnp.clip(jnp.round(x/s), -8, 7), round-half-to-even, rn divide
    return fminf(fmaxf(rintf(__fdiv_rn(x, s)), -8.0f), 7.0f);
}
__device__ __forceinline__ uint32_t bf16x2(float lo, float hi) {
    uint32_t r;
    asm("cvt.rn.bf16x2.f32 %0, %1, %2;" : "=r"(r) : "f"(hi), "f"(lo));
    return r;
}
__device__ __forceinline__ void mma16816(float* c, const uint32_t* a,
                                         const uint32_t* b) {
    asm volatile(
        "mma.sync.aligned.m16n8k16.row.col.f32.bf16.bf16.f32 "
        "{%0,%1,%2,%3}, {%4,%5,%6,%7}, {%8,%9}, {%0,%1,%2,%3};"
        : "+f"(c[0]), "+f"(c[1]), "+f"(c[2]), "+f"(c[3])
        : "r"(a[0]), "r"(a[1]), "r"(a[2]), "r"(a[3]), "r"(b[0]), "r"(b[1]));
}
#define CP_ASYNC16(dst_u32, src_ptr) \
    asm volatile("cp.async.cg.shared.global [%0], [%1], 16;" \
                 :: "r"(dst_u32), "l"(src_ptr) : "memory")
#define CP_COMMIT()  asm volatile("cp.async.commit_group;" ::: "memory")
#define CP_WAIT1()   asm volatile("cp.async.wait_group 1;" ::: "memory")

// ------------------------------ launch 1: X stats ---------------------------
__global__ void cmax_kernel(const float* __restrict__ X) {
    const int b = blockIdx.x;
    const int c = b >> 4, rg = (b >> 2) & 3, cg = b & 3;
    const int t = threadIdx.x;
    const int col4 = cg * 256 + t;                 // float4 column index
    const float4* p = reinterpret_cast<const float4*>(X) +
                      (size_t)(c * 256 + rg * 64) * 1024 + col4;
    float4 m4 = make_float4(0.f, 0.f, 0.f, 0.f);
#pragma unroll 8
    for (int r = 0; r < 64; r++) {
        float4 f = p[(size_t)r * 1024];
        m4.x = fmaxf(m4.x, fabsf(f.x)); m4.y = fmaxf(m4.y, fabsf(f.y));
        m4.z = fmaxf(m4.z, fabsf(f.z)); m4.w = fmaxf(m4.w, fabsf(f.w));
    }
    reinterpret_cast<float4*>(g_cmaxp)[(size_t)(rg * NCHUNK + c) * 1024 + col4] = m4;
    float m = fmaxf(fmaxf(m4.x, m4.y), fmaxf(m4.z, m4.w));
    __shared__ float red[256];
    red[t] = m;
    __syncthreads();
    for (int s = 128; s > 0; s >>= 1) {
        if (t < s) red[t] = fmaxf(red[t], red[t + s]);
        __syncthreads();
    }
    if (t == 0) g_part[c * 16 + rg * 4 + cg] = red[0];
}

// ------------------------------ launch 2: scales ----------------------------
__global__ void chunk_scales_kernel() {
    const int idx = blockIdx.x * 256 + threadIdx.x;   // NCHUNK*HID = 65536
    const int c = idx >> 12, ch = idx & 4095;
    float tmax = 0.0f;
#pragma unroll
    for (int j = 0; j < 16; j++) tmax = fmaxf(tmax, g_part[c * 16 + j]);
    if (ch == 0) g_tmaxf[c] = tmax;
    float cm = 0.0f;
#pragma unroll
    for (int rg = 0; rg < 4; rg++)
        cm = fmaxf(cm, g_cmaxp[(size_t)(rg * NCHUNK + c) * HID + ch]);
    int b = 0;
#pragma unroll
    for (int i = 0; i < 13; i++) b += (cm > ldexpf(tmax, i - 13)) ? 1 : 0;
    g_sx[idx]   = fmaxf(__fdiv_rn(ldexpf(tmax, b - 13), 7.0f), 1e-9f);
    g_mult[idx] = ldexpf(1.0f, b - 8);   // exact pow2 emit multiplier
}

// ------------------------------ launch 3: pack (W + X fused) ----------------
// blocks [0,2000): weight scale+pack, warp per ROW PAIR (v, v+8)
// blocks [2000,4048): activation pack (mt = b&31, kt = b>>5), float4 loads
__global__ void pack_kernel(const float* __restrict__ W,
                            const float* __restrict__ X) {
    if (blockIdx.x < 2000) {
        const int w = threadIdx.x >> 5, lane = threadIdx.x & 31;
        const int v = blockIdx.x * 16 + w;          // rows v and v+8
        const float4* rA = reinterpret_cast<const float4*>(W + (size_t)v * HID);
        const float4* rB = reinterpret_cast<const float4*>(W + (size_t)(v + 8) * HID);
        float mA = 0.0f, mB = 0.0f;
#pragma unroll
        for (int j = 0; j < 32; j++) {
            float4 a = rA[lane + j * 32];
            float4 b = rB[lane + j * 32];
            mA = fmaxf(mA, fmaxf(fmaxf(fabsf(a.x), fabsf(a.y)),
                                 fmaxf(fabsf(a.z), fabsf(a.w))));
            mB = fmaxf(mB, fmaxf(fmaxf(fabsf(b.x), fabsf(b.y)),
                                 fmaxf(fabsf(b.z), fabsf(b.w))));
        }
#pragma unroll
        for (int s = 16; s > 0; s >>= 1) {
            mA = fmaxf(mA, __shfl_xor_sync(0xFFFFFFFFu, mA, s));
            mB = fmaxf(mB, __shfl_xor_sync(0xFFFFFFFFu, mB, s));
        }
        const float scA = fmaxf(__fdiv_rn(__shfl_sync(0xFFFFFFFFu, mA, 0), 7.0f),
                                1e-9f);
        const float scB = fmaxf(__fdiv_rn(__shfl_sync(0xFFFFFFFFu, mB, 0), 7.0f),
                                1e-9f);
        if (lane == 0) { g_ws[v] = scA; g_ws[v + 8] = scB; }
        const int nt = v >> 7, np = ((v & 127) >> 3) >> 1, nn = v & 7;
        unsigned char* base = g_wb + ((size_t)nt << 14) + np * 512 + nn * 64;
#pragma unroll 2
        for (int i = 0; i < 8; i++) {
            const int c = i * 32 + lane;          // 16-k chunk index
            const int kt = c >> 2, ka = c & 3;
            const float4 a0 = rA[c * 4 + 0], a1 = rA[c * 4 + 1];
            const float4 a2 = rA[c * 4 + 2], a3 = rA[c * 4 + 3];
            const float4 b0 = rB[c * 4 + 0], b1 = rB[c * 4 + 1];
            const float4 b2 = rB[c * 4 + 2], b3 = rB[c * 4 + 3];
            uint4 u0, u1, u2, u3;
            u0.x = bf16x2(qclamp(a0.x, scA), qclamp(a0.y, scA));
            u0.y = bf16x2(qclamp(a2.x, scA), qclamp(a2.y, scA));
            u0.z = bf16x2(qclamp(b0.x, scB), qclamp(b0.y, scB));
            u0.w = bf16x2(qclamp(b2.x, scB), qclamp(b2.y, scB));
            u1.x = bf16x2(qclamp(a0.z, scA), qclamp(a0.w, scA));
            u1.y = bf16x2(qclamp(a2.z, scA), qclamp(a2.w, scA));
            u1.z = bf16x2(qclamp(b0.z, scB), qclamp(b0.w, scB));
            u1.w = bf16x2(qclamp(b2.z, scB), qclamp(b2.w, scB));
            u2.x = bf16x2(qclamp(a1.x, scA), qclamp(a1.y, scA));
            u2.y = bf16x2(qclamp(a3.x, scA), qclamp(a3.y, scA));
            u2.z = bf16x2(qclamp(b1.x, scB), qclamp(b1.y, scB));
            u2.w = bf16x2(qclamp(b3.x, scB), qclamp(b3.y, scB));
            u3.x = bf16x2(qclamp(a1.z, scA), qclamp(a1.w, scA));
            u3.y = bf16x2(qclamp(a3.z, scA), qclamp(a3.w, scA));
            u3.z = bf16x2(qclamp(b1.z, scB), qclamp(b1.w, scB));
            u3.w = bf16x2(qclamp(b3.z, scB), qclamp(b3.w, scB));
            unsigned char* dst =
                base + (size_t)kt * NT128 * 16384 + ka * 4096;
            *reinterpret_cast<uint4*>(dst)      = u0;  // p=0
            *reinterpret_cast<uint4*>(dst + 16) = u1;  // p=1
            *reinterpret_cast<uint4*>(dst + 32) = u2;  // p=2
            *reinterpret_cast<uint4*>(dst + 48) = u3;  // p=3
        }
    } else {
        // activation pack block (mt, kt): 128 rows x 64 K -> 16 KB fragment tile
        const int b2 = blockIdx.x - 2000;
        const int mt = b2 & 31, kt = b2 >> 5;
        const int t = threadIdx.x;
        __shared__ __align__(16) unsigned char stg[16384];
        const int r = t >> 1, hh = (t & 1) * 32;
        const int token = mt * 128 + r;
        const int chunk = token >> 8;
        const float4* x4 = reinterpret_cast<const float4*>(
            X + (size_t)token * HID + kt * 64 + hh);
        const float4* s4 = reinterpret_cast<const float4*>(
            g_sx + (size_t)chunk * HID + kt * 64 + hh);
        const float4* m4 = reinterpret_cast<const float4*>(
            g_mult + (size_t)chunk * HID + kt * 64 + hh);
        const int mm = r & 15, ma = r >> 4;
#pragma unroll
        for (int i = 0; i < 8; i++) {
            const float4 xv = x4[i], sv = s4[i], mv = m4[i];
            const int kl = hh + 4 * i;
            const int ka = kl >> 4, kk = kl & 15;
            const float e0 = qclamp(xv.x, sv.x) * mv.x;
            const float e1 = qclamp(xv.y, sv.y) * mv.y;
            const float e2 = qclamp(xv.z, sv.z) * mv.z;
            const float e3 = qclamp(xv.w, sv.w) * mv.w;
            const uint32_t base0 = (uint32_t)((ka * 8 + ma) * 512 +
                                   (mm & 7) * 64 + (mm >> 3) * 4);
            const uint32_t off0 = base0 + ((kk & 7) >> 1) * 16 + (kk >> 3) * 8;
            const int k2 = kk + 2;
            const uint32_t off1 = base0 + ((k2 & 7) >> 1) * 16 + (k2 >> 3) * 8;
            *reinterpret_cast<uint32_t*>(stg + off0) = bf16x2(e0, e1);
            *reinterpret_cast<uint32_t*>(stg + off1) = bf16x2(e2, e3);
        }
        __syncthreads();
        uint4* dst = reinterpret_cast<uint4*>(g_xa + ((size_t)(kt * MT + mt) << 14));
        const uint4* src = reinterpret_cast<const uint4*>(stg);
#pragma unroll
        for (int i = 0; i < 4; i++) dst[t + i * 256] = src[t + i * 256];
    }
}

// --------------------------------- GEMM (launch 4) --------------------------
// 128(M) x 128(N) CTA tile, 128 thr / 4 warps (2m x 2n) of 64x64,
// K stage 64, 3 stages x 32 KB, 2 CTAs/SM. R14 schedule with ONE change:
// the 16 cp.asyncs for kt+2 are spread across the ka loop (4 per ka, after
// each ka's MMAs) instead of a single end burst — drips LDGSTS into
// MMA-bound issue slots and avoids LSU contention at the barrier.
#define STAGES 3
#define STG_BYTES 32768   // A 16 KB + B 16 KB

__global__ void __launch_bounds__(128, 2) gemm_kernel(float* __restrict__ out) {
    extern __shared__ __align__(16) unsigned char dyn[];
    __shared__ float s_sw[128];
    const int tid = threadIdx.x;
    const int wid = tid >> 5, lid = tid & 31;
    const int mt = blockIdx.x, nt = blockIdx.y;
    const int wm = wid >> 1, wn = wid & 1;   // 2m x 2n warps of 64x64
    const uint32_t sbase = smem_u32(dyn);

    s_sw[tid] = g_ws[nt * 128 + tid];

    auto fetch = [&](int s, int kt) {
        const uint32_t d = sbase + s * STG_BYTES + tid * 16;
        const unsigned char* a = g_xa + (((size_t)kt * MT + mt) << 14) + tid * 16;
        const unsigned char* b = g_wb + (((size_t)kt * NT128 + nt) << 14) + tid * 16;
#pragma unroll
        for (int i = 0; i < 8; i++) CP_ASYNC16(d + i * 2048, a + i * 2048);
#pragma unroll
        for (int i = 0; i < 8; i++)
            CP_ASYNC16(d + 16384 + i * 2048, b + i * 2048);
    };

    float acc[4][8][4];
#pragma unroll
    for (int i = 0; i < 4; i++)
#pragma unroll
        for (int j = 0; j < 8; j++)
#pragma unroll
            for (int k = 0; k < 4; k++) acc[i][j][k] = 0.0f;

    fetch(0, 0); CP_COMMIT();
    fetch(1, 1); CP_COMMIT();

    int stage = 0;
#pragma unroll 1
    for (int kt = 0; kt < KT64; kt++) {
        CP_WAIT1();
        __syncthreads();
        const unsigned char* st = dyn + stage * STG_BYTES;
        // fetch target for kt+2 (stage consumed at kt-1; bar above protects)
        const bool dofetch = (kt + 2 < KT64);
        int ws = stage + 2; if (ws >= STAGES) ws -= STAGES;
        const uint32_t fd = sbase + ws * STG_BYTES + tid * 16;
        const unsigned char* fa =
            g_xa + (((size_t)(kt + 2) * MT + mt) << 14) + tid * 16;
        const unsigned char* fb =
            g_wb + (((size_t)(kt + 2) * NT128 + nt) << 14) + tid * 16;
#pragma unroll
        for (int ka = 0; ka < 4; ka++) {
            uint32_t af[4][4], bf[8][2];
#pragma unroll
            for (int ma = 0; ma < 4; ma++) {
                const uint4 q = *reinterpret_cast<const uint4*>(
                    st + (ka * 8 + wm * 4 + ma) * 512 + lid * 16);
                af[ma][0] = q.x; af[ma][1] = q.y; af[ma][2] = q.z; af[ma][3] = q.w;
            }
#pragma unroll
            for (int np = 0; np < 4; np++) {     // na pair: one LDS.128 for 2 na
                const uint4 q = *reinterpret_cast<const uint4*>(
                    st + 16384 + (ka * 8 + wn * 4 + np) * 512 + lid * 16);
                bf[2 * np][0] = q.x;     bf[2 * np][1] = q.y;
                bf[2 * np + 1][0] = q.z; bf[2 * np + 1][1] = q.w;
            }
#pragma unroll
            for (int ma = 0; ma < 4; ma++)
#pragma unroll
                for (int na = 0; na < 8; na++)
                    mma16816(acc[ma][na], af[ma], bf[na]);
            // drip 4 of the 16 cp.asyncs behind this ka's MMA wall
            if (dofetch) {
                CP_ASYNC16(fd + (2 * ka) * 2048,     fa + (2 * ka) * 2048);
                CP_ASYNC16(fd + (2 * ka + 1) * 2048, fa + (2 * ka + 1) * 2048);
                CP_ASYNC16(fd + 16384 + (2 * ka) * 2048,
                           fb + (2 * ka) * 2048);
                CP_ASYNC16(fd + 16384 + (2 * ka + 1) * 2048,
                           fb + (2 * ka + 1) * 2048);
            }
        }
        CP_COMMIT();
        if (++stage == STAGES) stage = 0;
    }

    // epilogue: acc * alpha[chunk] * sw[v]
    const float alpha = __fdiv_rn(g_tmaxf[mt >> 1], 7.0f) * 0.03125f;
    const int row_base = mt * 128 + wm * 64;
    const int col_cta = nt * 128;
#pragma unroll
    for (int ma = 0; ma < 4; ma++) {
#pragma unroll
        for (int na = 0; na < 8; na++) {
            const int r0 = row_base + ma * 16 + (lid >> 2);
            const int c0 = wn * 64 + na * 8 + (lid & 3) * 2;
            const float f0 = s_sw[c0] * alpha, f1 = s_sw[c0 + 1] * alpha;
            float* p = out + (size_t)r0 * VOCAB + col_cta + c0;
            float2 v0, v1;
            v0.x = acc[ma][na][0] * f0; v0.y = acc[ma][na][1] * f1;
            v1.x = acc[ma][na][2] * f0; v1.y = acc[ma][na][3] * f1;
            *reinterpret_cast<float2*>(p) = v0;
            *reinterpret_cast<float2*>(p + (size_t)8 * VOCAB) = v1;
        }
    }
}

// ------------------------------- launcher ----------------------------------
extern "C" void kernel_launch(void* const* d_in, const int* in_sizes, int n_in,
                              void* d_out, int out_size) {
    const float* hs = (const float*)d_in[0];   // [2,2048,4096]
    const float* W  = (const float*)d_in[1];   // [32000,4096]
    float* out = (float*)d_out;

    cudaFuncSetAttribute(gemm_kernel,
                         cudaFuncAttributeMaxDynamicSharedMemorySize,
                         STAGES * STG_BYTES);

    // 4 launches: gemm stays at ncu's profiled slot (-s 5 -c 1).
    cmax_kernel<<<256, 256>>>(hs);
    chunk_scales_kernel<<<NCHUNK * HID / 256, 256>>>();
    pack_kernel<<<4048, 256>>>(W, hs);
    gemm_kernel<<<dim3(MT, NT128), 128, STAGES * STG_BYTES>>>(out);
}